// round 14
// baseline (speedup 1.0000x reference)
#include <cuda_runtime.h>
#include <cuda_fp16.h>
#include <stdint.h>

// Problem dims
#define ROWS   32768          // T*B
#define I_DIM  256
#define H_DIM  512
#define C_DIM  1024
#define O_DIM  512
#define NCHUNK 16             // 64-col chunks of C_DIM

// Scratch (device globals: no allocation allowed)
__device__ float  g_h[(size_t)ROWS * H_DIM];        // fp32 hidden (exact-grade)
__device__ __half g_hf[(size_t)ROWS * H_DIM];       // fp16 hidden
__device__ __half g_w2h[(size_t)C_DIM * H_DIM];     // fp16 m2h_w
__device__ float  g_table[(size_t)C_DIM * O_DIM];   // log_softmax table

// per (row, 64-col chunk): max of c~ and candidate bitmask
__device__ float              g_tmax[(size_t)ROWS * NCHUNK];
__device__ unsigned long long g_tmask[(size_t)ROWS * NCHUNK];

// fp16 splits: x = x1 + x2 ; (i2m_w * 64) = v1 + v2
__device__ __half g_x1[(size_t)ROWS * I_DIM];
__device__ __half g_x2[(size_t)ROWS * I_DIM];
__device__ __half g_v1[(size_t)H_DIM * I_DIM];
__device__ __half g_v2[(size_t)H_DIM * I_DIM];

// ---------------------------------------------------------------------------
// PTX helpers (base sm_103 ISA: cp.async / ldmatrix / mma.sync)
// ---------------------------------------------------------------------------
__device__ __forceinline__ uint32_t smem_u32(const void* p) {
    uint32_t a;
    asm("{ .reg .u64 t; cvta.to.shared.u64 t, %1; cvt.u32.u64 %0, t; }" : "=r"(a) : "l"(p));
    return a;
}
#define CP_ASYNC16(dst, src) \
    asm volatile("cp.async.cg.shared.global [%0], [%1], 16;" :: "r"(dst), "l"(src) : "memory")
#define CP_COMMIT()  asm volatile("cp.async.commit_group;" ::: "memory")
#define CP_WAIT(n)   asm volatile("cp.async.wait_group %0;" :: "n"(n) : "memory")

__device__ __forceinline__ void ldsm_x4(uint32_t& r0, uint32_t& r1, uint32_t& r2, uint32_t& r3,
                                        uint32_t addr) {
    asm volatile("ldmatrix.sync.aligned.m8n8.x4.shared.b16 {%0,%1,%2,%3}, [%4];"
                 : "=r"(r0), "=r"(r1), "=r"(r2), "=r"(r3) : "r"(addr));
}
__device__ __forceinline__ void mma_f16(float* d, const uint32_t* a, const uint32_t* b) {
    asm volatile("mma.sync.aligned.m16n8k16.row.col.f32.f16.f16.f32 "
                 "{%0,%1,%2,%3}, {%4,%5,%6,%7}, {%8,%9}, {%0,%1,%2,%3};"
                 : "+f"(d[0]), "+f"(d[1]), "+f"(d[2]), "+f"(d[3])
                 : "r"(a[0]), "r"(a[1]), "r"(a[2]), "r"(a[3]), "r"(b[0]), "r"(b[1]));
}

// margin formula (shared by gemm2 mask + scan threshold)
__device__ __forceinline__ float marg(float t) { return 0.03f * fabsf(t) + 0.01f; }

// ---------------------------------------------------------------------------
// Merged prep kernel: split_x | split_w1(x64) | conv_w2(fp16) | build_table
// ---------------------------------------------------------------------------
#define NB_SPLITX  ((ROWS * I_DIM / 4) / 512)     // 4096
#define NB_SPLITW  ((H_DIM * I_DIM / 4) / 512)    // 64
#define NB_CONV    ((C_DIM * H_DIM / 4) / 512)    // 256
#define NB_TABLE   (C_DIM)                        // 1024
#define NB_PREP    (NB_SPLITX + NB_SPLITW + NB_CONV + NB_TABLE)

__device__ __forceinline__ void split2h(float v, __half& a, __half& b) {
    a = __float2half_rn(v);
    b = __float2half_rn(v - __half2float(a));
}

__global__ void __launch_bounds__(512)
prep(const float* __restrict__ x,   const float* __restrict__ w1,
     const float* __restrict__ w2,  const float* __restrict__ w3,
     const float* __restrict__ b3)
{
    const int b = blockIdx.x;
    if (b < NB_SPLITX) {
        size_t i = (size_t)b * 512 + threadIdx.x;
        float4 v = *(const float4*)(x + i * 4);
        __half a[4], bb[4];
        split2h(v.x, a[0], bb[0]);
        split2h(v.y, a[1], bb[1]);
        split2h(v.z, a[2], bb[2]);
        split2h(v.w, a[3], bb[3]);
        *(uint2*)(g_x1 + i * 4) = *(uint2*)a;
        *(uint2*)(g_x2 + i * 4) = *(uint2*)bb;
    } else if (b < NB_SPLITX + NB_SPLITW) {
        size_t i = (size_t)(b - NB_SPLITX) * 512 + threadIdx.x;
        float4 v = *(const float4*)(w1 + i * 4);
        __half a[4], bb[4];
        split2h(v.x * 64.0f, a[0], bb[0]);
        split2h(v.y * 64.0f, a[1], bb[1]);
        split2h(v.z * 64.0f, a[2], bb[2]);
        split2h(v.w * 64.0f, a[3], bb[3]);
        *(uint2*)(g_v1 + i * 4) = *(uint2*)a;
        *(uint2*)(g_v2 + i * 4) = *(uint2*)bb;
    } else if (b < NB_SPLITX + NB_SPLITW + NB_CONV) {
        size_t i = (size_t)(b - NB_SPLITX - NB_SPLITW) * 512 + threadIdx.x;
        float4 v = *(const float4*)(w2 + i * 4);
        __half hh[4] = { __float2half_rn(v.x), __float2half_rn(v.y),
                         __float2half_rn(v.z), __float2half_rn(v.w) };
        *(uint2*)(g_w2h + i * 4) = *(uint2*)hh;
    } else {
        __shared__ float wred[16];
        __shared__ float wsum[16];
        const int c = b - (NB_SPLITX + NB_SPLITW + NB_CONV);
        const int o = threadIdx.x;
        const int lw = o >> 5, lid = o & 31;
        float v = w3[(size_t)o * C_DIM + c] + b3[o];

        float m = v;
#pragma unroll
        for (int off = 16; off > 0; off >>= 1)
            m = fmaxf(m, __shfl_xor_sync(0xffffffffu, m, off));
        if (lid == 0) wred[lw] = m;
        __syncthreads();
        float mx = wred[0];
#pragma unroll
        for (int i = 1; i < 16; i++) mx = fmaxf(mx, wred[i]);

        float e = expf(v - mx);
        float s = e;
#pragma unroll
        for (int off = 16; off > 0; off >>= 1)
            s += __shfl_xor_sync(0xffffffffu, s, off);
        if (lid == 0) wsum[lw] = s;
        __syncthreads();
        float tot = 0.0f;
#pragma unroll
        for (int i = 0; i < 16; i++) tot += wsum[i];

        g_table[(size_t)c * O_DIM + o] = v - (logf(tot) + mx);
    }
}

// ---------------------------------------------------------------------------
// Pipelined HMMA GEMM core constants
// ---------------------------------------------------------------------------
#define BK        32
#define SROW      40
#define STAGE_HB  (128 * SROW * 2)        // 10240
#define STAGE_SZ  (2 * STAGE_HB)          // 20480
#define STAGES    5
#define SMEM_DYN  (STAGES * STAGE_SZ)     // 102400

// ---------------------------------------------------------------------------
// GEMM1 via fp16x3 HMMA (fp32-grade exact). NIT=24.
// ---------------------------------------------------------------------------
__global__ void __launch_bounds__(128, 2)
gemm1_mma(const float* __restrict__ bias)
{
    extern __shared__ __align__(16) unsigned char smem[];

    const int t   = threadIdx.x;
    const int wid = t >> 5, lid = t & 31;
    const int wm  = wid & 1;
    const int wn  = wid >> 1;
    const int bm  = blockIdx.y * 128, bn = blockIdx.x * 128;

    const __half* Aps[3] = { g_x1, g_x1, g_x2 };
    const __half* Bps[3] = { g_v1, g_v2, g_v1 };

    const uint32_t sbase = smem_u32(smem);

    const int rl[4] = { t >> 2, (t + 128) >> 2, (t + 256) >> 2, (t + 384) >> 2 };
    const int sg = t & 3;

    float d[4][8][4];
#pragma unroll
    for (int mi = 0; mi < 4; mi++)
#pragma unroll
        for (int ni = 0; ni < 8; ni++)
#pragma unroll
            for (int r = 0; r < 4; r++) d[mi][ni][r] = 0.0f;

    const int NIT = 3 * (I_DIM / BK);     // 24

#pragma unroll
    for (int p = 0; p < STAGES - 1; p++) {
        const int seg = p >> 3;
        const int k0  = (p & 7) * BK;
        const __half* Ap = Aps[seg];
        const __half* Bp = Bps[seg];
        const uint32_t dA = sbase + p * STAGE_SZ;
        const uint32_t dB = dA + STAGE_HB;
#pragma unroll
        for (int i = 0; i < 4; i++) {
            CP_ASYNC16(dA + rl[i]*80 + sg*16, Ap + (size_t)(bm + rl[i])*I_DIM + k0 + sg*8);
            CP_ASYNC16(dB + rl[i]*80 + sg*16, Bp + (size_t)(bn + rl[i])*I_DIM + k0 + sg*8);
        }
        CP_COMMIT();
    }

    const int rowA = wm*64 + (lid & 15);
    const int colAofs = (lid < 16) ? 0 : 8;
    const int rowB = wn*64 + ((lid >> 4) & 1)*8 + (lid & 7);
    const int colBofs = ((lid >> 3) & 1)*8;

    int stage = 0;
    for (int kt = 0; kt < NIT; kt++) {
        CP_WAIT(STAGES - 2);
        __syncthreads();

        const uint32_t aB = sbase + stage * STAGE_SZ;
        const uint32_t bB = aB + STAGE_HB;
#pragma unroll
        for (int ks = 0; ks < BK; ks += 16) {
            uint32_t a[4][4];
#pragma unroll
            for (int mi = 0; mi < 4; mi++)
                ldsm_x4(a[mi][0], a[mi][1], a[mi][2], a[mi][3],
                        aB + (uint32_t)(rowA + mi*16) * 80 + (uint32_t)(ks + colAofs) * 2);
            uint32_t b[8][2];
#pragma unroll
            for (int np = 0; np < 4; np++) {
                uint32_t q0, q1, q2, q3;
                ldsm_x4(q0, q1, q2, q3,
                        bB + (uint32_t)(rowB + np*16) * 80 + (uint32_t)(ks + colBofs) * 2);
                b[np*2][0] = q0; b[np*2][1] = q1;
                b[np*2+1][0] = q2; b[np*2+1][1] = q3;
            }
#pragma unroll
            for (int mi = 0; mi < 4; mi++)
#pragma unroll
                for (int ni = 0; ni < 8; ni++)
                    mma_f16(d[mi][ni], a[mi], b[ni]);
        }

        const int kn = kt + STAGES - 1;
        if (kn < NIT) {
            const int seg = kn >> 3;
            const int k0  = (kn & 7) * BK;
            const __half* Ap = Aps[seg];
            const __half* Bp = Bps[seg];
            const int ws = (stage + STAGES - 1) % STAGES;
            const uint32_t dA = sbase + ws * STAGE_SZ;
            const uint32_t dB = dA + STAGE_HB;
#pragma unroll
            for (int i = 0; i < 4; i++) {
                CP_ASYNC16(dA + rl[i]*80 + sg*16, Ap + (size_t)(bm + rl[i])*I_DIM + k0 + sg*8);
                CP_ASYNC16(dB + rl[i]*80 + sg*16, Bp + (size_t)(bn + rl[i])*I_DIM + k0 + sg*8);
            }
        }
        CP_COMMIT();

        stage = (stage + 1 == STAGES) ? 0 : stage + 1;
    }

    const float INV64 = 0.015625f;
    const int cbase = bn + wn*64 + (lid & 3) * 2;
#pragma unroll
    for (int ni = 0; ni < 8; ni++) {
        const int col = cbase + ni*8;
        const float b0 = __ldg(bias + col), b1 = __ldg(bias + col + 1);
#pragma unroll
        for (int mi = 0; mi < 4; mi++) {
            const int r0 = bm + wm*64 + mi*16 + (lid >> 2);
            float v00 = fmaxf(fmaf(d[mi][ni][0], INV64, b0), 0.0f);
            float v01 = fmaxf(fmaf(d[mi][ni][1], INV64, b1), 0.0f);
            float v10 = fmaxf(fmaf(d[mi][ni][2], INV64, b0), 0.0f);
            float v11 = fmaxf(fmaf(d[mi][ni][3], INV64, b1), 0.0f);
            *(float2*)(g_h + (size_t)r0 * H_DIM + col)       = make_float2(v00, v01);
            *(float2*)(g_h + (size_t)(r0 + 8) * H_DIM + col) = make_float2(v10, v11);
            *(__half2*)(g_hf + (size_t)r0 * H_DIM + col)       = __floats2half2_rn(v00, v01);
            *(__half2*)(g_hf + (size_t)(r0 + 8) * H_DIM + col) = __floats2half2_rn(v10, v11);
        }
    }
}

// ---------------------------------------------------------------------------
// GEMM2: HMMA (fp16 in, fp32 acc); epilogue emits per-(row, 64-chunk)
// (max, candidate-mask).  NIT=16.
// ---------------------------------------------------------------------------
__global__ void __launch_bounds__(128, 2)
gemm2_mma(const float* __restrict__ bias)
{
    extern __shared__ __align__(16) unsigned char smem[];

    const int t   = threadIdx.x;
    const int wid = t >> 5, lid = t & 31;
    const int wm  = wid & 1;
    const int wn  = wid >> 1;
    const int bm  = blockIdx.y * 128, bn = blockIdx.x * 128;

    const uint32_t sbase = smem_u32(smem);

    const int rl[4] = { t >> 2, (t + 128) >> 2, (t + 256) >> 2, (t + 384) >> 2 };
    const int sg = t & 3;

    float d[4][8][4];
#pragma unroll
    for (int mi = 0; mi < 4; mi++)
#pragma unroll
        for (int ni = 0; ni < 8; ni++)
#pragma unroll
            for (int r = 0; r < 4; r++) d[mi][ni][r] = 0.0f;

    const int NIT = H_DIM / BK;           // 16

#pragma unroll
    for (int p = 0; p < STAGES - 1; p++) {
        const int k0 = p * BK;
        const uint32_t dA = sbase + p * STAGE_SZ;
        const uint32_t dB = dA + STAGE_HB;
#pragma unroll
        for (int i = 0; i < 4; i++) {
            CP_ASYNC16(dA + rl[i]*80 + sg*16, g_hf  + (size_t)(bm + rl[i])*H_DIM + k0 + sg*8);
            CP_ASYNC16(dB + rl[i]*80 + sg*16, g_w2h + (size_t)(bn + rl[i])*H_DIM + k0 + sg*8);
        }
        CP_COMMIT();
    }

    const int rowA = wm*64 + (lid & 15);
    const int colAofs = (lid < 16) ? 0 : 8;
    const int rowB = wn*64 + ((lid >> 4) & 1)*8 + (lid & 7);
    const int colBofs = ((lid >> 3) & 1)*8;

    int stage = 0;
    for (int kt = 0; kt < NIT; kt++) {
        CP_WAIT(STAGES - 2);
        __syncthreads();

        const uint32_t aB = sbase + stage * STAGE_SZ;
        const uint32_t bB = aB + STAGE_HB;
#pragma unroll
        for (int ks = 0; ks < BK; ks += 16) {
            uint32_t a[4][4];
#pragma unroll
            for (int mi = 0; mi < 4; mi++)
                ldsm_x4(a[mi][0], a[mi][1], a[mi][2], a[mi][3],
                        aB + (uint32_t)(rowA + mi*16) * 80 + (uint32_t)(ks + colAofs) * 2);
            uint32_t b[8][2];
#pragma unroll
            for (int np = 0; np < 4; np++) {
                uint32_t q0, q1, q2, q3;
                ldsm_x4(q0, q1, q2, q3,
                        bB + (uint32_t)(rowB + np*16) * 80 + (uint32_t)(ks + colBofs) * 2);
                b[np*2][0] = q0; b[np*2][1] = q1;
                b[np*2+1][0] = q2; b[np*2+1][1] = q3;
            }
#pragma unroll
            for (int mi = 0; mi < 4; mi++)
#pragma unroll
                for (int ni = 0; ni < 8; ni++)
                    mma_f16(d[mi][ni], a[mi], b[ni]);
        }

        const int kn = kt + STAGES - 1;
        if (kn < NIT) {
            const int k0 = kn * BK;
            const int ws = (stage + STAGES - 1) % STAGES;
            const uint32_t dA = sbase + ws * STAGE_SZ;
            const uint32_t dB = dA + STAGE_HB;
#pragma unroll
            for (int i = 0; i < 4; i++) {
                CP_ASYNC16(dA + rl[i]*80 + sg*16, g_hf  + (size_t)(bm + rl[i])*H_DIM + k0 + sg*8);
                CP_ASYNC16(dB + rl[i]*80 + sg*16, g_w2h + (size_t)(bn + rl[i])*H_DIM + k0 + sg*8);
            }
        }
        CP_COMMIT();

        stage = (stage + 1 == STAGES) ? 0 : stage + 1;
    }

    // ---- epilogue: per-row (max, mask) over this warp's 64 cols ----
    const int q = lid >> 2;
    const int s = lid & 3;
    const int chunk = (bn >> 6) + wn;

    float bc[8][2];
#pragma unroll
    for (int ni = 0; ni < 8; ni++) {
        const int col = bn + wn*64 + ni*8 + s*2;
        bc[ni][0] = __ldg(bias + col);
        bc[ni][1] = __ldg(bias + col + 1);
    }

#pragma unroll
    for (int mi = 0; mi < 4; mi++) {
        float vmA = -1e30f, vmB = -1e30f;
#pragma unroll
        for (int ni = 0; ni < 8; ni++) {
            vmA = fmaxf(vmA, fmaxf(d[mi][ni][0] + bc[ni][0], d[mi][ni][1] + bc[ni][1]));
            vmB = fmaxf(vmB, fmaxf(d[mi][ni][2] + bc[ni][0], d[mi][ni][3] + bc[ni][1]));
        }
#pragma unroll
        for (int off = 1; off <= 2; off <<= 1) {
            vmA = fmaxf(vmA, __shfl_xor_sync(0xffffffffu, vmA, off));
            vmB = fmaxf(vmB, __shfl_xor_sync(0xffffffffu, vmB, off));
        }
        const float thrA = vmA - marg(vmA);
        const float thrB = vmB - marg(vmB);

        unsigned long long mA = 0ull, mB = 0ull;
#pragma unroll
        for (int ni = 0; ni < 8; ni++) {
            const int bit = ni*8 + s*2;
            if (d[mi][ni][0] + bc[ni][0] >= thrA) mA |= 1ull << bit;
            if (d[mi][ni][1] + bc[ni][1] >= thrA) mA |= 1ull << (bit + 1);
            if (d[mi][ni][2] + bc[ni][0] >= thrB) mB |= 1ull << bit;
            if (d[mi][ni][3] + bc[ni][1] >= thrB) mB |= 1ull << (bit + 1);
        }
#pragma unroll
        for (int off = 1; off <= 2; off <<= 1) {
            mA |= __shfl_xor_sync(0xffffffffu, mA, off);
            mB |= __shfl_xor_sync(0xffffffffu, mB, off);
        }

        if (s == 0) {
            const int rA = bm + wm*64 + mi*16 + q;
            const int rB = rA + 8;
            g_tmax [(size_t)rA * NCHUNK + chunk] = vmA;
            g_tmask[(size_t)rA * NCHUNK + chunk] = mA;
            g_tmax [(size_t)rB * NCHUNK + chunk] = vmB;
            g_tmask[(size_t)rB * NCHUNK + chunk] = mB;
        }
    }
}

// ---------------------------------------------------------------------------
// Scan: 32 rows per block. Phase 1 bulk-loads tmax/tmask to smem (high MLP);
// phase 2 resolves each row from smem (n==1 fast path; fp32 refine otherwise);
// phase 3 gathers table row -> out. One warp per row x 4 iterations.
// ---------------------------------------------------------------------------
#define SCAN_ROWS 32

__global__ void __launch_bounds__(256)
scan_out(const float* __restrict__ w, const float* __restrict__ b,
         float* __restrict__ out)
{
    __shared__ float              s_tmax[SCAN_ROWS][NCHUNK];
    __shared__ unsigned long long s_tmask[SCAN_ROWS][NCHUNK];
    __shared__ int cnt[8];
    __shared__ int cand[8][64];

    const int t = threadIdx.x, wid = t >> 5, lid = t & 31;
    const int rbase = blockIdx.x * SCAN_ROWS;

    // phase 1: bulk load (512 floats + 512 u64, coalesced, 2 each per thread)
    {
        const float* ts = g_tmax + (size_t)rbase * NCHUNK;
        ((float*)s_tmax)[t]       = ts[t];
        ((float*)s_tmax)[t + 256] = ts[t + 256];
        const unsigned long long* ms = g_tmask + (size_t)rbase * NCHUNK;
        ((unsigned long long*)s_tmask)[t]       = ms[t];
        ((unsigned long long*)s_tmask)[t + 256] = ms[t + 256];
    }
    __syncthreads();

    // phase 2+3: each warp resolves 4 rows
    for (int rr = 0; rr < 4; rr++) {
        const int lr = wid * 4 + rr;
        const int row = rbase + lr;

        float tm = (lid < NCHUNK) ? s_tmax[lr][lid] : -1e30f;
        float mx = tm;
#pragma unroll
        for (int off = 16; off > 0; off >>= 1)
            mx = fmaxf(mx, __shfl_xor_sync(0xffffffffu, mx, off));
        const float thr = mx - marg(mx);

        if (lid == 0) cnt[wid] = 0;
        __syncwarp();

#pragma unroll
        for (int ch = 0; ch < NCHUNK; ch++) {
            float cm = __shfl_sync(0xffffffffu, tm, ch);
            if (cm >= thr) {
                unsigned long long mask = s_tmask[lr][ch];
                if ((mask >> lid) & 1ull) {
                    int p = atomicAdd(&cnt[wid], 1);
                    if (p < 64) cand[wid][p] = ch*64 + lid;
                }
                if ((mask >> (lid + 32)) & 1ull) {
                    int p = atomicAdd(&cnt[wid], 1);
                    if (p < 64) cand[wid][p] = ch*64 + 32 + lid;
                }
            }
        }
        __syncwarp();
        int n = min(cnt[wid], 64);

        int bidx;
        if (n == 1) {
            // single candidate above threshold -> provably the winner
            bidx = cand[wid][0];
        } else {
            const float4* h4 = (const float4*)(g_h + (size_t)row * H_DIM);
            float4 hreg[4];
#pragma unroll
            for (int i = 0; i < 4; i++) hreg[i] = h4[lid + i * 32];

            float best = -1e30f; bidx = C_DIM;
            for (int ci = 0; ci < n; ci++) {
                int j = cand[wid][ci];
                const float4* w4 = (const float4*)(w + (size_t)j * H_DIM);
                float s = 0.0f;
#pragma unroll
                for (int i = 0; i < 4; i++) {
                    float4 wv = w4[lid + i * 32];
                    s = fmaf(hreg[i].x, wv.x, s);
                    s = fmaf(hreg[i].y, wv.y, s);
                    s = fmaf(hreg[i].z, wv.z, s);
                    s = fmaf(hreg[i].w, wv.w, s);
                }
#pragma unroll
                for (int off = 16; off > 0; off >>= 1)
                    s += __shfl_xor_sync(0xffffffffu, s, off);
                s += b[j];
                if (s > best || (s == best && j < bidx)) { best = s; bidx = j; }
            }
            bidx = __shfl_sync(0xffffffffu, bidx, 0);
        }

        const float4* src = (const float4*)(g_table + (size_t)bidx * O_DIM);
        float4* dst = (float4*)(out + (size_t)row * O_DIM);
#pragma unroll
        for (int i = 0; i < 4; i++)
            dst[lid + i * 32] = src[lid + i * 32];
    }
}

extern "C" void kernel_launch(void* const* d_in, const int* in_sizes, int n_in,
                              void* d_out, int out_size)
{
    const float* x     = (const float*)d_in[0];
    const float* i2m_w = (const float*)d_in[2];
    const float* i2m_b = (const float*)d_in[3];
    const float* m2h_w = (const float*)d_in[4];
    const float* m2h_b = (const float*)d_in[5];
    const float* h2o_w = (const float*)d_in[6];
    const float* h2o_b = (const float*)d_in[7];
    float* out = (float*)d_out;

    cudaFuncSetAttribute(gemm1_mma, cudaFuncAttributeMaxDynamicSharedMemorySize, SMEM_DYN);
    cudaFuncSetAttribute(gemm2_mma, cudaFuncAttributeMaxDynamicSharedMemorySize, SMEM_DYN);

    // merged prep
    prep<<<NB_PREP, 512>>>(x, i2m_w, m2h_w, h2o_w, h2o_b);

    // 1) h = relu(x @ i2m_w^T + b)  (fp16x3, fp32-grade)
    gemm1_mma<<<dim3(H_DIM/128, ROWS/128), 128, SMEM_DYN>>>(i2m_b);

    // 2) c~ max+mask per (row, chunk)  (fp16 in, fp32 acc)
    gemm2_mma<<<dim3(C_DIM/128, ROWS/128), 128, SMEM_DYN>>>(m2h_b);

    // 3) winner per row (fp32-verified when ambiguous) + output write
    scan_out<<<ROWS/SCAN_ROWS, 256>>>(m2h_w, m2h_b, out);
}

// round 15
// speedup vs baseline: 1.0214x; 1.0214x over previous
#include <cuda_runtime.h>
#include <cuda_fp16.h>
#include <stdint.h>

// Problem dims
#define ROWS   32768          // T*B
#define I_DIM  256
#define H_DIM  512
#define C_DIM  1024
#define O_DIM  512
#define NCHUNK 16             // 64-col chunks of C_DIM

// Scratch (device globals: no allocation allowed)
__device__ float  g_h[(size_t)ROWS * H_DIM];        // fp32 hidden (exact-grade)
__device__ __half g_hf[(size_t)ROWS * H_DIM];       // fp16 hidden
__device__ __half g_w2h[(size_t)C_DIM * H_DIM];     // fp16 m2h_w
__device__ float  g_table[(size_t)C_DIM * O_DIM];   // log_softmax table

// per (row, 64-col chunk): max of c~ and candidate bitmask
__device__ float              g_tmax[(size_t)ROWS * NCHUNK];
__device__ unsigned long long g_tmask[(size_t)ROWS * NCHUNK];

// fp16 splits: x = x1 + x2 ; (i2m_w * 64) = v1 + v2
__device__ __half g_x1[(size_t)ROWS * I_DIM];
__device__ __half g_x2[(size_t)ROWS * I_DIM];
__device__ __half g_v1[(size_t)H_DIM * I_DIM];
__device__ __half g_v2[(size_t)H_DIM * I_DIM];

// ---------------------------------------------------------------------------
// PTX helpers (base sm_103 ISA: cp.async / ldmatrix / mma.sync)
// ---------------------------------------------------------------------------
__device__ __forceinline__ uint32_t smem_u32(const void* p) {
    uint32_t a;
    asm("{ .reg .u64 t; cvta.to.shared.u64 t, %1; cvt.u32.u64 %0, t; }" : "=r"(a) : "l"(p));
    return a;
}
#define CP_ASYNC16(dst, src) \
    asm volatile("cp.async.cg.shared.global [%0], [%1], 16;" :: "r"(dst), "l"(src) : "memory")
#define CP_COMMIT()  asm volatile("cp.async.commit_group;" ::: "memory")
#define CP_WAIT(n)   asm volatile("cp.async.wait_group %0;" :: "n"(n) : "memory")

__device__ __forceinline__ void ldsm_x4(uint32_t& r0, uint32_t& r1, uint32_t& r2, uint32_t& r3,
                                        uint32_t addr) {
    asm volatile("ldmatrix.sync.aligned.m8n8.x4.shared.b16 {%0,%1,%2,%3}, [%4];"
                 : "=r"(r0), "=r"(r1), "=r"(r2), "=r"(r3) : "r"(addr));
}
__device__ __forceinline__ void mma_f16(float* d, const uint32_t* a, const uint32_t* b) {
    asm volatile("mma.sync.aligned.m16n8k16.row.col.f32.f16.f16.f32 "
                 "{%0,%1,%2,%3}, {%4,%5,%6,%7}, {%8,%9}, {%0,%1,%2,%3};"
                 : "+f"(d[0]), "+f"(d[1]), "+f"(d[2]), "+f"(d[3])
                 : "r"(a[0]), "r"(a[1]), "r"(a[2]), "r"(a[3]), "r"(b[0]), "r"(b[1]));
}

// margin formula (shared by gemm2 mask + scan threshold)
__device__ __forceinline__ float marg(float t) { return 0.03f * fabsf(t) + 0.01f; }

// ---------------------------------------------------------------------------
// Merged prep kernel: split_x | split_w1(x64) | conv_w2(fp16) | build_table
// ---------------------------------------------------------------------------
#define NB_SPLITX  ((ROWS * I_DIM / 4) / 512)     // 4096
#define NB_SPLITW  ((H_DIM * I_DIM / 4) / 512)    // 64
#define NB_CONV    ((C_DIM * H_DIM / 4) / 512)    // 256
#define NB_TABLE   (C_DIM)                        // 1024
#define NB_PREP    (NB_SPLITX + NB_SPLITW + NB_CONV + NB_TABLE)

__device__ __forceinline__ void split2h(float v, __half& a, __half& b) {
    a = __float2half_rn(v);
    b = __float2half_rn(v - __half2float(a));
}

__global__ void __launch_bounds__(512)
prep(const float* __restrict__ x,   const float* __restrict__ w1,
     const float* __restrict__ w2,  const float* __restrict__ w3,
     const float* __restrict__ b3)
{
    const int b = blockIdx.x;
    if (b < NB_SPLITX) {
        size_t i = (size_t)b * 512 + threadIdx.x;
        float4 v = *(const float4*)(x + i * 4);
        __half a[4], bb[4];
        split2h(v.x, a[0], bb[0]);
        split2h(v.y, a[1], bb[1]);
        split2h(v.z, a[2], bb[2]);
        split2h(v.w, a[3], bb[3]);
        *(uint2*)(g_x1 + i * 4) = *(uint2*)a;
        *(uint2*)(g_x2 + i * 4) = *(uint2*)bb;
    } else if (b < NB_SPLITX + NB_SPLITW) {
        size_t i = (size_t)(b - NB_SPLITX) * 512 + threadIdx.x;
        float4 v = *(const float4*)(w1 + i * 4);
        __half a[4], bb[4];
        split2h(v.x * 64.0f, a[0], bb[0]);
        split2h(v.y * 64.0f, a[1], bb[1]);
        split2h(v.z * 64.0f, a[2], bb[2]);
        split2h(v.w * 64.0f, a[3], bb[3]);
        *(uint2*)(g_v1 + i * 4) = *(uint2*)a;
        *(uint2*)(g_v2 + i * 4) = *(uint2*)bb;
    } else if (b < NB_SPLITX + NB_SPLITW + NB_CONV) {
        size_t i = (size_t)(b - NB_SPLITX - NB_SPLITW) * 512 + threadIdx.x;
        float4 v = *(const float4*)(w2 + i * 4);
        __half hh[4] = { __float2half_rn(v.x), __float2half_rn(v.y),
                         __float2half_rn(v.z), __float2half_rn(v.w) };
        *(uint2*)(g_w2h + i * 4) = *(uint2*)hh;
    } else {
        __shared__ float wred[16];
        __shared__ float wsum[16];
        const int c = b - (NB_SPLITX + NB_SPLITW + NB_CONV);
        const int o = threadIdx.x;
        const int lw = o >> 5, lid = o & 31;
        float v = w3[(size_t)o * C_DIM + c] + b3[o];

        float m = v;
#pragma unroll
        for (int off = 16; off > 0; off >>= 1)
            m = fmaxf(m, __shfl_xor_sync(0xffffffffu, m, off));
        if (lid == 0) wred[lw] = m;
        __syncthreads();
        float mx = wred[0];
#pragma unroll
        for (int i = 1; i < 16; i++) mx = fmaxf(mx, wred[i]);

        float e = expf(v - mx);
        float s = e;
#pragma unroll
        for (int off = 16; off > 0; off >>= 1)
            s += __shfl_xor_sync(0xffffffffu, s, off);
        if (lid == 0) wsum[lw] = s;
        __syncthreads();
        float tot = 0.0f;
#pragma unroll
        for (int i = 0; i < 16; i++) tot += wsum[i];

        g_table[(size_t)c * O_DIM + o] = v - (logf(tot) + mx);
    }
}

// ---------------------------------------------------------------------------
// Pipelined HMMA GEMM core constants
// ---------------------------------------------------------------------------
#define BK        32
#define SROW      40
#define STAGE_HB  (128 * SROW * 2)        // 10240
#define STAGE_SZ  (2 * STAGE_HB)          // 20480
#define STAGES    5
#define SMEM_DYN  (STAGES * STAGE_SZ)     // 102400

// ---------------------------------------------------------------------------
// GEMM1 via fp16x3 HMMA (fp32-grade exact). NIT=24.
// ---------------------------------------------------------------------------
__global__ void __launch_bounds__(128, 2)
gemm1_mma(const float* __restrict__ bias)
{
    extern __shared__ __align__(16) unsigned char smem[];

    const int t   = threadIdx.x;
    const int wid = t >> 5, lid = t & 31;
    const int wm  = wid & 1;
    const int wn  = wid >> 1;
    const int bm  = blockIdx.y * 128, bn = blockIdx.x * 128;

    const __half* Aps[3] = { g_x1, g_x1, g_x2 };
    const __half* Bps[3] = { g_v1, g_v2, g_v1 };

    const uint32_t sbase = smem_u32(smem);

    const int rl[4] = { t >> 2, (t + 128) >> 2, (t + 256) >> 2, (t + 384) >> 2 };
    const int sg = t & 3;

    float d[4][8][4];
#pragma unroll
    for (int mi = 0; mi < 4; mi++)
#pragma unroll
        for (int ni = 0; ni < 8; ni++)
#pragma unroll
            for (int r = 0; r < 4; r++) d[mi][ni][r] = 0.0f;

    const int NIT = 3 * (I_DIM / BK);     // 24

#pragma unroll
    for (int p = 0; p < STAGES - 1; p++) {
        const int seg = p >> 3;
        const int k0  = (p & 7) * BK;
        const __half* Ap = Aps[seg];
        const __half* Bp = Bps[seg];
        const uint32_t dA = sbase + p * STAGE_SZ;
        const uint32_t dB = dA + STAGE_HB;
#pragma unroll
        for (int i = 0; i < 4; i++) {
            CP_ASYNC16(dA + rl[i]*80 + sg*16, Ap + (size_t)(bm + rl[i])*I_DIM + k0 + sg*8);
            CP_ASYNC16(dB + rl[i]*80 + sg*16, Bp + (size_t)(bn + rl[i])*I_DIM + k0 + sg*8);
        }
        CP_COMMIT();
    }

    const int rowA = wm*64 + (lid & 15);
    const int colAofs = (lid < 16) ? 0 : 8;
    const int rowB = wn*64 + ((lid >> 4) & 1)*8 + (lid & 7);
    const int colBofs = ((lid >> 3) & 1)*8;

    int stage = 0;
    for (int kt = 0; kt < NIT; kt++) {
        CP_WAIT(STAGES - 2);
        __syncthreads();

        const uint32_t aB = sbase + stage * STAGE_SZ;
        const uint32_t bB = aB + STAGE_HB;
#pragma unroll
        for (int ks = 0; ks < BK; ks += 16) {
            uint32_t a[4][4];
#pragma unroll
            for (int mi = 0; mi < 4; mi++)
                ldsm_x4(a[mi][0], a[mi][1], a[mi][2], a[mi][3],
                        aB + (uint32_t)(rowA + mi*16) * 80 + (uint32_t)(ks + colAofs) * 2);
            uint32_t b[8][2];
#pragma unroll
            for (int np = 0; np < 4; np++) {
                uint32_t q0, q1, q2, q3;
                ldsm_x4(q0, q1, q2, q3,
                        bB + (uint32_t)(rowB + np*16) * 80 + (uint32_t)(ks + colBofs) * 2);
                b[np*2][0] = q0; b[np*2][1] = q1;
                b[np*2+1][0] = q2; b[np*2+1][1] = q3;
            }
#pragma unroll
            for (int mi = 0; mi < 4; mi++)
#pragma unroll
                for (int ni = 0; ni < 8; ni++)
                    mma_f16(d[mi][ni], a[mi], b[ni]);
        }

        const int kn = kt + STAGES - 1;
        if (kn < NIT) {
            const int seg = kn >> 3;
            const int k0  = (kn & 7) * BK;
            const __half* Ap = Aps[seg];
            const __half* Bp = Bps[seg];
            const int ws = (stage + STAGES - 1) % STAGES;
            const uint32_t dA = sbase + ws * STAGE_SZ;
            const uint32_t dB = dA + STAGE_HB;
#pragma unroll
            for (int i = 0; i < 4; i++) {
                CP_ASYNC16(dA + rl[i]*80 + sg*16, Ap + (size_t)(bm + rl[i])*I_DIM + k0 + sg*8);
                CP_ASYNC16(dB + rl[i]*80 + sg*16, Bp + (size_t)(bn + rl[i])*I_DIM + k0 + sg*8);
            }
        }
        CP_COMMIT();

        stage = (stage + 1 == STAGES) ? 0 : stage + 1;
    }

    const float INV64 = 0.015625f;
    const int cbase = bn + wn*64 + (lid & 3) * 2;
#pragma unroll
    for (int ni = 0; ni < 8; ni++) {
        const int col = cbase + ni*8;
        const float b0 = __ldg(bias + col), b1 = __ldg(bias + col + 1);
#pragma unroll
        for (int mi = 0; mi < 4; mi++) {
            const int r0 = bm + wm*64 + mi*16 + (lid >> 2);
            float v00 = fmaxf(fmaf(d[mi][ni][0], INV64, b0), 0.0f);
            float v01 = fmaxf(fmaf(d[mi][ni][1], INV64, b1), 0.0f);
            float v10 = fmaxf(fmaf(d[mi][ni][2], INV64, b0), 0.0f);
            float v11 = fmaxf(fmaf(d[mi][ni][3], INV64, b1), 0.0f);
            *(float2*)(g_h + (size_t)r0 * H_DIM + col)       = make_float2(v00, v01);
            *(float2*)(g_h + (size_t)(r0 + 8) * H_DIM + col) = make_float2(v10, v11);
            *(__half2*)(g_hf + (size_t)r0 * H_DIM + col)       = __floats2half2_rn(v00, v01);
            *(__half2*)(g_hf + (size_t)(r0 + 8) * H_DIM + col) = __floats2half2_rn(v10, v11);
        }
    }
}

// ---------------------------------------------------------------------------
// GEMM2: HMMA (fp16 in, fp32 acc); epilogue emits per-(row, 64-chunk)
// (max, candidate-mask).  NIT=16.
// ---------------------------------------------------------------------------
__global__ void __launch_bounds__(128, 2)
gemm2_mma(const float* __restrict__ bias)
{
    extern __shared__ __align__(16) unsigned char smem[];

    const int t   = threadIdx.x;
    const int wid = t >> 5, lid = t & 31;
    const int wm  = wid & 1;
    const int wn  = wid >> 1;
    const int bm  = blockIdx.y * 128, bn = blockIdx.x * 128;

    const uint32_t sbase = smem_u32(smem);

    const int rl[4] = { t >> 2, (t + 128) >> 2, (t + 256) >> 2, (t + 384) >> 2 };
    const int sg = t & 3;

    float d[4][8][4];
#pragma unroll
    for (int mi = 0; mi < 4; mi++)
#pragma unroll
        for (int ni = 0; ni < 8; ni++)
#pragma unroll
            for (int r = 0; r < 4; r++) d[mi][ni][r] = 0.0f;

    const int NIT = H_DIM / BK;           // 16

#pragma unroll
    for (int p = 0; p < STAGES - 1; p++) {
        const int k0 = p * BK;
        const uint32_t dA = sbase + p * STAGE_SZ;
        const uint32_t dB = dA + STAGE_HB;
#pragma unroll
        for (int i = 0; i < 4; i++) {
            CP_ASYNC16(dA + rl[i]*80 + sg*16, g_hf  + (size_t)(bm + rl[i])*H_DIM + k0 + sg*8);
            CP_ASYNC16(dB + rl[i]*80 + sg*16, g_w2h + (size_t)(bn + rl[i])*H_DIM + k0 + sg*8);
        }
        CP_COMMIT();
    }

    const int rowA = wm*64 + (lid & 15);
    const int colAofs = (lid < 16) ? 0 : 8;
    const int rowB = wn*64 + ((lid >> 4) & 1)*8 + (lid & 7);
    const int colBofs = ((lid >> 3) & 1)*8;

    int stage = 0;
    for (int kt = 0; kt < NIT; kt++) {
        CP_WAIT(STAGES - 2);
        __syncthreads();

        const uint32_t aB = sbase + stage * STAGE_SZ;
        const uint32_t bB = aB + STAGE_HB;
#pragma unroll
        for (int ks = 0; ks < BK; ks += 16) {
            uint32_t a[4][4];
#pragma unroll
            for (int mi = 0; mi < 4; mi++)
                ldsm_x4(a[mi][0], a[mi][1], a[mi][2], a[mi][3],
                        aB + (uint32_t)(rowA + mi*16) * 80 + (uint32_t)(ks + colAofs) * 2);
            uint32_t b[8][2];
#pragma unroll
            for (int np = 0; np < 4; np++) {
                uint32_t q0, q1, q2, q3;
                ldsm_x4(q0, q1, q2, q3,
                        bB + (uint32_t)(rowB + np*16) * 80 + (uint32_t)(ks + colBofs) * 2);
                b[np*2][0] = q0; b[np*2][1] = q1;
                b[np*2+1][0] = q2; b[np*2+1][1] = q3;
            }
#pragma unroll
            for (int mi = 0; mi < 4; mi++)
#pragma unroll
                for (int ni = 0; ni < 8; ni++)
                    mma_f16(d[mi][ni], a[mi], b[ni]);
        }

        const int kn = kt + STAGES - 1;
        if (kn < NIT) {
            const int k0 = kn * BK;
            const int ws = (stage + STAGES - 1) % STAGES;
            const uint32_t dA = sbase + ws * STAGE_SZ;
            const uint32_t dB = dA + STAGE_HB;
#pragma unroll
            for (int i = 0; i < 4; i++) {
                CP_ASYNC16(dA + rl[i]*80 + sg*16, g_hf  + (size_t)(bm + rl[i])*H_DIM + k0 + sg*8);
                CP_ASYNC16(dB + rl[i]*80 + sg*16, g_w2h + (size_t)(bn + rl[i])*H_DIM + k0 + sg*8);
            }
        }
        CP_COMMIT();

        stage = (stage + 1 == STAGES) ? 0 : stage + 1;
    }

    // ---- epilogue: per-row (max, mask) over this warp's 64 cols ----
    const int q = lid >> 2;
    const int s = lid & 3;
    const int chunk = (bn >> 6) + wn;

    float bc[8][2];
#pragma unroll
    for (int ni = 0; ni < 8; ni++) {
        const int col = bn + wn*64 + ni*8 + s*2;
        bc[ni][0] = __ldg(bias + col);
        bc[ni][1] = __ldg(bias + col + 1);
    }

#pragma unroll
    for (int mi = 0; mi < 4; mi++) {
        float vmA = -1e30f, vmB = -1e30f;
#pragma unroll
        for (int ni = 0; ni < 8; ni++) {
            vmA = fmaxf(vmA, fmaxf(d[mi][ni][0] + bc[ni][0], d[mi][ni][1] + bc[ni][1]));
            vmB = fmaxf(vmB, fmaxf(d[mi][ni][2] + bc[ni][0], d[mi][ni][3] + bc[ni][1]));
        }
#pragma unroll
        for (int off = 1; off <= 2; off <<= 1) {
            vmA = fmaxf(vmA, __shfl_xor_sync(0xffffffffu, vmA, off));
            vmB = fmaxf(vmB, __shfl_xor_sync(0xffffffffu, vmB, off));
        }
        const float thrA = vmA - marg(vmA);
        const float thrB = vmB - marg(vmB);

        unsigned long long mA = 0ull, mB = 0ull;
#pragma unroll
        for (int ni = 0; ni < 8; ni++) {
            const int bit = ni*8 + s*2;
            if (d[mi][ni][0] + bc[ni][0] >= thrA) mA |= 1ull << bit;
            if (d[mi][ni][1] + bc[ni][1] >= thrA) mA |= 1ull << (bit + 1);
            if (d[mi][ni][2] + bc[ni][0] >= thrB) mB |= 1ull << bit;
            if (d[mi][ni][3] + bc[ni][1] >= thrB) mB |= 1ull << (bit + 1);
        }
#pragma unroll
        for (int off = 1; off <= 2; off <<= 1) {
            mA |= __shfl_xor_sync(0xffffffffu, mA, off);
            mB |= __shfl_xor_sync(0xffffffffu, mB, off);
        }

        if (s == 0) {
            const int rA = bm + wm*64 + mi*16 + q;
            const int rB = rA + 8;
            g_tmax [(size_t)rA * NCHUNK + chunk] = vmA;
            g_tmask[(size_t)rA * NCHUNK + chunk] = mA;
            g_tmax [(size_t)rB * NCHUNK + chunk] = vmB;
            g_tmask[(size_t)rB * NCHUNK + chunk] = mB;
        }
    }
}

// ---------------------------------------------------------------------------
// Scan: register/shuffle-based. Lane<16 holds (tmax, tmask) for its chunk.
// n==1 -> ballot/ffs fast path (provably the winner). Else shfl-gather +
// fp32-exact refine. One warp per row, 8 warps per block.
// ---------------------------------------------------------------------------
__global__ void __launch_bounds__(256)
scan_out(const float* __restrict__ w, const float* __restrict__ b,
         float* __restrict__ out)
{
    __shared__ int cnt[8];
    __shared__ int cand[8][64];
    const int wid = threadIdx.x >> 5, lid = threadIdx.x & 31;
    const int row = blockIdx.x * 8 + wid;

    float tm = -1e30f;
    unsigned long long msk = 0ull;
    if (lid < NCHUNK) {
        tm  = g_tmax [(size_t)row * NCHUNK + lid];
        msk = g_tmask[(size_t)row * NCHUNK + lid];
    }
    float mx = tm;
#pragma unroll
    for (int off = 16; off > 0; off >>= 1)
        mx = fmaxf(mx, __shfl_xor_sync(0xffffffffu, mx, off));
    const float thr = mx - marg(mx);

    const bool qual = (lid < NCHUNK) && (tm >= thr);
    int nl = qual ? __popcll(msk) : 0;
    int n = nl;
#pragma unroll
    for (int off = 16; off > 0; off >>= 1)
        n += __shfl_xor_sync(0xffffffffu, n, off);

    int bidx;
    if (n == 1) {
        // exactly one candidate above threshold -> provably the winner
        unsigned bal = __ballot_sync(0xffffffffu, nl > 0);
        int src = __ffs(bal) - 1;
        unsigned long long m = __shfl_sync(0xffffffffu, msk, src);
        bidx = src * 64 + (__ffsll(m) - 1);
    } else {
        // gather candidates via shuffle (no global mask re-read)
        if (lid == 0) cnt[wid] = 0;
        __syncwarp();
#pragma unroll
        for (int ch = 0; ch < NCHUNK; ch++) {
            float cm = __shfl_sync(0xffffffffu, tm, ch);
            if (cm >= thr) {
                unsigned long long mask = __shfl_sync(0xffffffffu, msk, ch);
                if ((mask >> lid) & 1ull) {
                    int p = atomicAdd(&cnt[wid], 1);
                    if (p < 64) cand[wid][p] = ch*64 + lid;
                }
                if ((mask >> (lid + 32)) & 1ull) {
                    int p = atomicAdd(&cnt[wid], 1);
                    if (p < 64) cand[wid][p] = ch*64 + 32 + lid;
                }
            }
        }
        __syncwarp();
        int nn = min(cnt[wid], 64);

        const float4* h4 = (const float4*)(g_h + (size_t)row * H_DIM);
        float4 hreg[4];
#pragma unroll
        for (int i = 0; i < 4; i++) hreg[i] = h4[lid + i * 32];

        float best = -1e30f; bidx = C_DIM;
        for (int ci = 0; ci < nn; ci++) {
            int j = cand[wid][ci];
            const float4* w4 = (const float4*)(w + (size_t)j * H_DIM);
            float s = 0.0f;
#pragma unroll
            for (int i = 0; i < 4; i++) {
                float4 wv = w4[lid + i * 32];
                s = fmaf(hreg[i].x, wv.x, s);
                s = fmaf(hreg[i].y, wv.y, s);
                s = fmaf(hreg[i].z, wv.z, s);
                s = fmaf(hreg[i].w, wv.w, s);
            }
#pragma unroll
            for (int off = 16; off > 0; off >>= 1)
                s += __shfl_xor_sync(0xffffffffu, s, off);
            s += b[j];
            if (s > best || (s == best && j < bidx)) { best = s; bidx = j; }
        }
        bidx = __shfl_sync(0xffffffffu, bidx, 0);
    }

    const float4* src4 = (const float4*)(g_table + (size_t)bidx * O_DIM);
    float4* dst = (float4*)(out + (size_t)row * O_DIM);
#pragma unroll
    for (int i = 0; i < 4; i++)
        dst[lid + i * 32] = src4[lid + i * 32];
}

extern "C" void kernel_launch(void* const* d_in, const int* in_sizes, int n_in,
                              void* d_out, int out_size)
{
    const float* x     = (const float*)d_in[0];
    const float* i2m_w = (const float*)d_in[2];
    const float* i2m_b = (const float*)d_in[3];
    const float* m2h_w = (const float*)d_in[4];
    const float* m2h_b = (const float*)d_in[5];
    const float* h2o_w = (const float*)d_in[6];
    const float* h2o_b = (const float*)d_in[7];
    float* out = (float*)d_out;

    cudaFuncSetAttribute(gemm1_mma, cudaFuncAttributeMaxDynamicSharedMemorySize, SMEM_DYN);
    cudaFuncSetAttribute(gemm2_mma, cudaFuncAttributeMaxDynamicSharedMemorySize, SMEM_DYN);

    // merged prep
    prep<<<NB_PREP, 512>>>(x, i2m_w, m2h_w, h2o_w, h2o_b);

    // 1) h = relu(x @ i2m_w^T + b)  (fp16x3, fp32-grade)
    gemm1_mma<<<dim3(H_DIM/128, ROWS/128), 128, SMEM_DYN>>>(i2m_b);

    // 2) c~ max+mask per (row, chunk)  (fp16 in, fp32 acc)
    gemm2_mma<<<dim3(C_DIM/128, ROWS/128), 128, SMEM_DYN>>>(m2h_b);

    // 3) winner per row (fp32-verified when ambiguous) + output write
    scan_out<<<ROWS/8, 256>>>(m2h_w, m2h_b, out);
}

// round 16
// speedup vs baseline: 1.0379x; 1.0162x over previous
#include <cuda_runtime.h>
#include <cuda_fp16.h>
#include <stdint.h>

// Problem dims
#define ROWS   32768          // T*B
#define I_DIM  256
#define H_DIM  512
#define C_DIM  1024
#define O_DIM  512
#define NCHUNK 16             // 64-col chunks of C_DIM
#define NMB    (ROWS / 128)   // 256 row-tiles

// Scratch (device globals: no allocation allowed)
__device__ float  g_h[(size_t)ROWS * H_DIM];        // fp32 hidden (exact-grade)
__device__ __half g_hf[(size_t)ROWS * H_DIM];       // fp16 hidden
__device__ __half g_w2h[(size_t)C_DIM * H_DIM];     // fp16 m2h_w
__device__ float  g_table[(size_t)C_DIM * O_DIM];   // log_softmax table
__device__ unsigned g_cnt[NMB];                     // gemm1->gemm2 rendezvous

// per (row, 64-col chunk): max of c~ and candidate bitmask
__device__ float              g_tmax[(size_t)ROWS * NCHUNK];
__device__ unsigned long long g_tmask[(size_t)ROWS * NCHUNK];

// fp16 splits: x = x1 + x2 ; (i2m_w * 64) = v1 + v2
__device__ __half g_x1[(size_t)ROWS * I_DIM];
__device__ __half g_x2[(size_t)ROWS * I_DIM];
__device__ __half g_v1[(size_t)H_DIM * I_DIM];
__device__ __half g_v2[(size_t)H_DIM * I_DIM];

// ---------------------------------------------------------------------------
// PTX helpers (base sm_103 ISA: cp.async / ldmatrix / mma.sync)
// ---------------------------------------------------------------------------
__device__ __forceinline__ uint32_t smem_u32(const void* p) {
    uint32_t a;
    asm("{ .reg .u64 t; cvta.to.shared.u64 t, %1; cvt.u32.u64 %0, t; }" : "=r"(a) : "l"(p));
    return a;
}
#define CP_ASYNC16(dst, src) \
    asm volatile("cp.async.cg.shared.global [%0], [%1], 16;" :: "r"(dst), "l"(src) : "memory")
#define CP_COMMIT()  asm volatile("cp.async.commit_group;" ::: "memory")
#define CP_WAIT(n)   asm volatile("cp.async.wait_group %0;" :: "n"(n) : "memory")

__device__ __forceinline__ void ldsm_x4(uint32_t& r0, uint32_t& r1, uint32_t& r2, uint32_t& r3,
                                        uint32_t addr) {
    asm volatile("ldmatrix.sync.aligned.m8n8.x4.shared.b16 {%0,%1,%2,%3}, [%4];"
                 : "=r"(r0), "=r"(r1), "=r"(r2), "=r"(r3) : "r"(addr));
}
__device__ __forceinline__ void mma_f16(float* d, const uint32_t* a, const uint32_t* b) {
    asm volatile("mma.sync.aligned.m16n8k16.row.col.f32.f16.f16.f32 "
                 "{%0,%1,%2,%3}, {%4,%5,%6,%7}, {%8,%9}, {%0,%1,%2,%3};"
                 : "+f"(d[0]), "+f"(d[1]), "+f"(d[2]), "+f"(d[3])
                 : "r"(a[0]), "r"(a[1]), "r"(a[2]), "r"(a[3]), "r"(b[0]), "r"(b[1]));
}

// margin formula (shared by gemm2 mask + scan threshold)
__device__ __forceinline__ float marg(float t) { return 0.03f * fabsf(t) + 0.01f; }

// ---------------------------------------------------------------------------
// Merged prep kernel: split_x | split_w1(x64) | conv_w2(fp16) | build_table
// | zero rendezvous counters
// ---------------------------------------------------------------------------
#define NB_SPLITX  ((ROWS * I_DIM / 4) / 512)     // 4096
#define NB_SPLITW  ((H_DIM * I_DIM / 4) / 512)    // 64
#define NB_CONV    ((C_DIM * H_DIM / 4) / 512)    // 256
#define NB_TABLE   (C_DIM)                        // 1024
#define NB_PREP    (NB_SPLITX + NB_SPLITW + NB_CONV + NB_TABLE + 1)

__device__ __forceinline__ void split2h(float v, __half& a, __half& b) {
    a = __float2half_rn(v);
    b = __float2half_rn(v - __half2float(a));
}

__global__ void __launch_bounds__(512)
prep(const float* __restrict__ x,   const float* __restrict__ w1,
     const float* __restrict__ w2,  const float* __restrict__ w3,
     const float* __restrict__ b3)
{
    const int b = blockIdx.x;
    if (b < NB_SPLITX) {
        size_t i = (size_t)b * 512 + threadIdx.x;
        float4 v = *(const float4*)(x + i * 4);
        __half a[4], bb[4];
        split2h(v.x, a[0], bb[0]);
        split2h(v.y, a[1], bb[1]);
        split2h(v.z, a[2], bb[2]);
        split2h(v.w, a[3], bb[3]);
        *(uint2*)(g_x1 + i * 4) = *(uint2*)a;
        *(uint2*)(g_x2 + i * 4) = *(uint2*)bb;
    } else if (b < NB_SPLITX + NB_SPLITW) {
        size_t i = (size_t)(b - NB_SPLITX) * 512 + threadIdx.x;
        float4 v = *(const float4*)(w1 + i * 4);
        __half a[4], bb[4];
        split2h(v.x * 64.0f, a[0], bb[0]);
        split2h(v.y * 64.0f, a[1], bb[1]);
        split2h(v.z * 64.0f, a[2], bb[2]);
        split2h(v.w * 64.0f, a[3], bb[3]);
        *(uint2*)(g_v1 + i * 4) = *(uint2*)a;
        *(uint2*)(g_v2 + i * 4) = *(uint2*)bb;
    } else if (b < NB_SPLITX + NB_SPLITW + NB_CONV) {
        size_t i = (size_t)(b - NB_SPLITX - NB_SPLITW) * 512 + threadIdx.x;
        float4 v = *(const float4*)(w2 + i * 4);
        __half hh[4] = { __float2half_rn(v.x), __float2half_rn(v.y),
                         __float2half_rn(v.z), __float2half_rn(v.w) };
        *(uint2*)(g_w2h + i * 4) = *(uint2*)hh;
    } else if (b < NB_SPLITX + NB_SPLITW + NB_CONV + NB_TABLE) {
        __shared__ float wred[16];
        __shared__ float wsum[16];
        const int c = b - (NB_SPLITX + NB_SPLITW + NB_CONV);
        const int o = threadIdx.x;
        const int lw = o >> 5, lid = o & 31;
        float v = w3[(size_t)o * C_DIM + c] + b3[o];

        float m = v;
#pragma unroll
        for (int off = 16; off > 0; off >>= 1)
            m = fmaxf(m, __shfl_xor_sync(0xffffffffu, m, off));
        if (lid == 0) wred[lw] = m;
        __syncthreads();
        float mx = wred[0];
#pragma unroll
        for (int i = 1; i < 16; i++) mx = fmaxf(mx, wred[i]);

        float e = expf(v - mx);
        float s = e;
#pragma unroll
        for (int off = 16; off > 0; off >>= 1)
            s += __shfl_xor_sync(0xffffffffu, s, off);
        if (lid == 0) wsum[lw] = s;
        __syncthreads();
        float tot = 0.0f;
#pragma unroll
        for (int i = 0; i < 16; i++) tot += wsum[i];

        g_table[(size_t)c * O_DIM + o] = v - (logf(tot) + mx);
    } else {
        // zero the gemm1->gemm2 rendezvous counters
        if (threadIdx.x < NMB) g_cnt[threadIdx.x] = 0u;
    }
}

// ---------------------------------------------------------------------------
// Pipelined HMMA GEMM core constants
// ---------------------------------------------------------------------------
#define BK        32
#define SROW      40
#define STAGE_HB  (128 * SROW * 2)        // 10240
#define STAGE_SZ  (2 * STAGE_HB)          // 20480
#define STAGES    5
#define SMEM_DYN  (STAGES * STAGE_SZ)     // 102400

#define G1_BLOCKS 1024                    // 4 n-tiles x 256 m-tiles
#define G2_BLOCKS 2048                    // 8 n-tiles x 256 m-tiles

// ---------------------------------------------------------------------------
// Fused GEMM kernel. blockIdx.x < G1_BLOCKS: gemm1 tile (fp16x3, NIT=24),
// release-signals g_cnt[bm]. Else: gemm2 tile, acquire-spins g_cnt[bm]==4.
// ---------------------------------------------------------------------------
__global__ void __launch_bounds__(128, 2)
gemm_fused(const float* __restrict__ bias1, const float* __restrict__ bias2)
{
    extern __shared__ __align__(16) unsigned char smem[];

    const int t   = threadIdx.x;
    const int wid = t >> 5, lid = t & 31;
    const int wm  = wid & 1;
    const int wn  = wid >> 1;

    const uint32_t sbase = smem_u32(smem);
    const int rl[4] = { t >> 2, (t + 128) >> 2, (t + 256) >> 2, (t + 384) >> 2 };
    const int sg = t & 3;

    float d[4][8][4];
#pragma unroll
    for (int mi = 0; mi < 4; mi++)
#pragma unroll
        for (int ni = 0; ni < 8; ni++)
#pragma unroll
            for (int r = 0; r < 4; r++) d[mi][ni][r] = 0.0f;

    const int rowA = wm*64 + (lid & 15);
    const int colAofs = (lid < 16) ? 0 : 8;
    const int rowB = wn*64 + ((lid >> 4) & 1)*8 + (lid & 7);
    const int colBofs = ((lid >> 3) & 1)*8;

    if (blockIdx.x < G1_BLOCKS) {
        // ================= GEMM1 (fp16x3) =================
        const int bmi = blockIdx.x >> 2;
        const int bm  = bmi * 128;
        const int bn  = (blockIdx.x & 3) * 128;

        const __half* Aps[3] = { g_x1, g_x1, g_x2 };
        const __half* Bps[3] = { g_v1, g_v2, g_v1 };
        const int NIT = 3 * (I_DIM / BK);     // 24

#pragma unroll
        for (int p = 0; p < STAGES - 1; p++) {
            const int seg = p >> 3;
            const int k0  = (p & 7) * BK;
            const __half* Ap = Aps[seg];
            const __half* Bp = Bps[seg];
            const uint32_t dA = sbase + p * STAGE_SZ;
            const uint32_t dB = dA + STAGE_HB;
#pragma unroll
            for (int i = 0; i < 4; i++) {
                CP_ASYNC16(dA + rl[i]*80 + sg*16, Ap + (size_t)(bm + rl[i])*I_DIM + k0 + sg*8);
                CP_ASYNC16(dB + rl[i]*80 + sg*16, Bp + (size_t)(bn + rl[i])*I_DIM + k0 + sg*8);
            }
            CP_COMMIT();
        }

        int stage = 0;
        for (int kt = 0; kt < NIT; kt++) {
            CP_WAIT(STAGES - 2);
            __syncthreads();

            const uint32_t aB = sbase + stage * STAGE_SZ;
            const uint32_t bB = aB + STAGE_HB;
#pragma unroll
            for (int ks = 0; ks < BK; ks += 16) {
                uint32_t a[4][4];
#pragma unroll
                for (int mi = 0; mi < 4; mi++)
                    ldsm_x4(a[mi][0], a[mi][1], a[mi][2], a[mi][3],
                            aB + (uint32_t)(rowA + mi*16) * 80 + (uint32_t)(ks + colAofs) * 2);
                uint32_t b[8][2];
#pragma unroll
                for (int np = 0; np < 4; np++) {
                    uint32_t q0, q1, q2, q3;
                    ldsm_x4(q0, q1, q2, q3,
                            bB + (uint32_t)(rowB + np*16) * 80 + (uint32_t)(ks + colBofs) * 2);
                    b[np*2][0] = q0; b[np*2][1] = q1;
                    b[np*2+1][0] = q2; b[np*2+1][1] = q3;
                }
#pragma unroll
                for (int mi = 0; mi < 4; mi++)
#pragma unroll
                    for (int ni = 0; ni < 8; ni++)
                        mma_f16(d[mi][ni], a[mi], b[ni]);
            }

            const int kn = kt + STAGES - 1;
            if (kn < NIT) {
                const int seg = kn >> 3;
                const int k0  = (kn & 7) * BK;
                const __half* Ap = Aps[seg];
                const __half* Bp = Bps[seg];
                const int ws = (stage + STAGES - 1) % STAGES;
                const uint32_t dA = sbase + ws * STAGE_SZ;
                const uint32_t dB = dA + STAGE_HB;
#pragma unroll
                for (int i = 0; i < 4; i++) {
                    CP_ASYNC16(dA + rl[i]*80 + sg*16, Ap + (size_t)(bm + rl[i])*I_DIM + k0 + sg*8);
                    CP_ASYNC16(dB + rl[i]*80 + sg*16, Bp + (size_t)(bn + rl[i])*I_DIM + k0 + sg*8);
                }
            }
            CP_COMMIT();

            stage = (stage + 1 == STAGES) ? 0 : stage + 1;
        }

        const float INV64 = 0.015625f;
        const int cbase = bn + wn*64 + (lid & 3) * 2;
#pragma unroll
        for (int ni = 0; ni < 8; ni++) {
            const int col = cbase + ni*8;
            const float b0 = __ldg(bias1 + col), b1 = __ldg(bias1 + col + 1);
#pragma unroll
            for (int mi = 0; mi < 4; mi++) {
                const int r0 = bm + wm*64 + mi*16 + (lid >> 2);
                float v00 = fmaxf(fmaf(d[mi][ni][0], INV64, b0), 0.0f);
                float v01 = fmaxf(fmaf(d[mi][ni][1], INV64, b1), 0.0f);
                float v10 = fmaxf(fmaf(d[mi][ni][2], INV64, b0), 0.0f);
                float v11 = fmaxf(fmaf(d[mi][ni][3], INV64, b1), 0.0f);
                *(float2*)(g_h + (size_t)r0 * H_DIM + col)       = make_float2(v00, v01);
                *(float2*)(g_h + (size_t)(r0 + 8) * H_DIM + col) = make_float2(v10, v11);
                *(__half2*)(g_hf + (size_t)r0 * H_DIM + col)       = __floats2half2_rn(v00, v01);
                *(__half2*)(g_hf + (size_t)(r0 + 8) * H_DIM + col) = __floats2half2_rn(v10, v11);
            }
        }

        // release-signal: h rows [bm, bm+128) of this n-tile are done
        __threadfence();
        __syncthreads();
        if (t == 0) atomicAdd(&g_cnt[bmi], 1u);

    } else {
        // ================= GEMM2 (fp16 in, fp32 acc) =================
        const int j   = blockIdx.x - G1_BLOCKS;
        const int bmi = j >> 3;
        const int bm  = bmi * 128;
        const int bn  = (j & 7) * 128;

        // acquire-spin until all 4 gemm1 n-tiles for this row-tile completed
        if (t == 0) {
            unsigned v;
            do {
                asm volatile("ld.acquire.gpu.global.u32 %0, [%1];"
                             : "=r"(v) : "l"(&g_cnt[bmi]) : "memory");
            } while (v < 4u);
        }
        __syncthreads();

        const int NIT = H_DIM / BK;           // 16

#pragma unroll
        for (int p = 0; p < STAGES - 1; p++) {
            const int k0 = p * BK;
            const uint32_t dA = sbase + p * STAGE_SZ;
            const uint32_t dB = dA + STAGE_HB;
#pragma unroll
            for (int i = 0; i < 4; i++) {
                CP_ASYNC16(dA + rl[i]*80 + sg*16, g_hf  + (size_t)(bm + rl[i])*H_DIM + k0 + sg*8);
                CP_ASYNC16(dB + rl[i]*80 + sg*16, g_w2h + (size_t)(bn + rl[i])*H_DIM + k0 + sg*8);
            }
            CP_COMMIT();
        }

        int stage = 0;
        for (int kt = 0; kt < NIT; kt++) {
            CP_WAIT(STAGES - 2);
            __syncthreads();

            const uint32_t aB = sbase + stage * STAGE_SZ;
            const uint32_t bB = aB + STAGE_HB;
#pragma unroll
            for (int ks = 0; ks < BK; ks += 16) {
                uint32_t a[4][4];
#pragma unroll
                for (int mi = 0; mi < 4; mi++)
                    ldsm_x4(a[mi][0], a[mi][1], a[mi][2], a[mi][3],
                            aB + (uint32_t)(rowA + mi*16) * 80 + (uint32_t)(ks + colAofs) * 2);
                uint32_t b[8][2];
#pragma unroll
                for (int np = 0; np < 4; np++) {
                    uint32_t q0, q1, q2, q3;
                    ldsm_x4(q0, q1, q2, q3,
                            bB + (uint32_t)(rowB + np*16) * 80 + (uint32_t)(ks + colBofs) * 2);
                    b[np*2][0] = q0; b[np*2][1] = q1;
                    b[np*2+1][0] = q2; b[np*2+1][1] = q3;
                }
#pragma unroll
                for (int mi = 0; mi < 4; mi++)
#pragma unroll
                    for (int ni = 0; ni < 8; ni++)
                        mma_f16(d[mi][ni], a[mi], b[ni]);
            }

            const int kn = kt + STAGES - 1;
            if (kn < NIT) {
                const int k0 = kn * BK;
                const int ws = (stage + STAGES - 1) % STAGES;
                const uint32_t dA = sbase + ws * STAGE_SZ;
                const uint32_t dB = dA + STAGE_HB;
#pragma unroll
                for (int i = 0; i < 4; i++) {
                    CP_ASYNC16(dA + rl[i]*80 + sg*16, g_hf  + (size_t)(bm + rl[i])*H_DIM + k0 + sg*8);
                    CP_ASYNC16(dB + rl[i]*80 + sg*16, g_w2h + (size_t)(bn + rl[i])*H_DIM + k0 + sg*8);
                }
            }
            CP_COMMIT();

            stage = (stage + 1 == STAGES) ? 0 : stage + 1;
        }

        // epilogue: per-row (max, mask) over this warp's 64 cols
        const int q = lid >> 2;
        const int s = lid & 3;
        const int chunk = (bn >> 6) + wn;

        float bc[8][2];
#pragma unroll
        for (int ni = 0; ni < 8; ni++) {
            const int col = bn + wn*64 + ni*8 + s*2;
            bc[ni][0] = __ldg(bias2 + col);
            bc[ni][1] = __ldg(bias2 + col + 1);
        }

#pragma unroll
        for (int mi = 0; mi < 4; mi++) {
            float vmA = -1e30f, vmB = -1e30f;
#pragma unroll
            for (int ni = 0; ni < 8; ni++) {
                vmA = fmaxf(vmA, fmaxf(d[mi][ni][0] + bc[ni][0], d[mi][ni][1] + bc[ni][1]));
                vmB = fmaxf(vmB, fmaxf(d[mi][ni][2] + bc[ni][0], d[mi][ni][3] + bc[ni][1]));
            }
#pragma unroll
            for (int off = 1; off <= 2; off <<= 1) {
                vmA = fmaxf(vmA, __shfl_xor_sync(0xffffffffu, vmA, off));
                vmB = fmaxf(vmB, __shfl_xor_sync(0xffffffffu, vmB, off));
            }
            const float thrA = vmA - marg(vmA);
            const float thrB = vmB - marg(vmB);

            unsigned long long mA = 0ull, mB = 0ull;
#pragma unroll
            for (int ni = 0; ni < 8; ni++) {
                const int bit = ni*8 + s*2;
                if (d[mi][ni][0] + bc[ni][0] >= thrA) mA |= 1ull << bit;
                if (d[mi][ni][1] + bc[ni][1] >= thrA) mA |= 1ull << (bit + 1);
                if (d[mi][ni][2] + bc[ni][0] >= thrB) mB |= 1ull << bit;
                if (d[mi][ni][3] + bc[ni][1] >= thrB) mB |= 1ull << (bit + 1);
            }
#pragma unroll
            for (int off = 1; off <= 2; off <<= 1) {
                mA |= __shfl_xor_sync(0xffffffffu, mA, off);
                mB |= __shfl_xor_sync(0xffffffffu, mB, off);
            }

            if (s == 0) {
                const int rA = bm + wm*64 + mi*16 + q;
                const int rB = rA + 8;
                g_tmax [(size_t)rA * NCHUNK + chunk] = vmA;
                g_tmask[(size_t)rA * NCHUNK + chunk] = mA;
                g_tmax [(size_t)rB * NCHUNK + chunk] = vmB;
                g_tmask[(size_t)rB * NCHUNK + chunk] = mB;
            }
        }
    }
}

// ---------------------------------------------------------------------------
// Scan: register/shuffle-based. Lane<16 holds (tmax, tmask) for its chunk.
// n==1 -> ballot/ffs fast path. Else shfl-gather + fp32-exact refine.
// ---------------------------------------------------------------------------
__global__ void __launch_bounds__(256)
scan_out(const float* __restrict__ w, const float* __restrict__ b,
         float* __restrict__ out)
{
    __shared__ int cnt[8];
    __shared__ int cand[8][64];
    const int wid = threadIdx.x >> 5, lid = threadIdx.x & 31;
    const int row = blockIdx.x * 8 + wid;

    float tm = -1e30f;
    unsigned long long msk = 0ull;
    if (lid < NCHUNK) {
        tm  = g_tmax [(size_t)row * NCHUNK + lid];
        msk = g_tmask[(size_t)row * NCHUNK + lid];
    }
    float mx = tm;
#pragma unroll
    for (int off = 16; off > 0; off >>= 1)
        mx = fmaxf(mx, __shfl_xor_sync(0xffffffffu, mx, off));
    const float thr = mx - marg(mx);

    const bool qual = (lid < NCHUNK) && (tm >= thr);
    int nl = qual ? __popcll(msk) : 0;
    int n = nl;
#pragma unroll
    for (int off = 16; off > 0; off >>= 1)
        n += __shfl_xor_sync(0xffffffffu, n, off);

    int bidx;
    if (n == 1) {
        unsigned bal = __ballot_sync(0xffffffffu, nl > 0);
        int src = __ffs(bal) - 1;
        unsigned long long m = __shfl_sync(0xffffffffu, msk, src);
        bidx = src * 64 + (__ffsll(m) - 1);
    } else {
        if (lid == 0) cnt[wid] = 0;
        __syncwarp();
#pragma unroll
        for (int ch = 0; ch < NCHUNK; ch++) {
            float cm = __shfl_sync(0xffffffffu, tm, ch);
            if (cm >= thr) {
                unsigned long long mask = __shfl_sync(0xffffffffu, msk, ch);
                if ((mask >> lid) & 1ull) {
                    int p = atomicAdd(&cnt[wid], 1);
                    if (p < 64) cand[wid][p] = ch*64 + lid;
                }
                if ((mask >> (lid + 32)) & 1ull) {
                    int p = atomicAdd(&cnt[wid], 1);
                    if (p < 64) cand[wid][p] = ch*64 + 32 + lid;
                }
            }
        }
        __syncwarp();
        int nn = min(cnt[wid], 64);

        const float4* h4 = (const float4*)(g_h + (size_t)row * H_DIM);
        float4 hreg[4];
#pragma unroll
        for (int i = 0; i < 4; i++) hreg[i] = h4[lid + i * 32];

        float best = -1e30f; bidx = C_DIM;
        for (int ci = 0; ci < nn; ci++) {
            int j = cand[wid][ci];
            const float4* w4 = (const float4*)(w + (size_t)j * H_DIM);
            float s = 0.0f;
#pragma unroll
            for (int i = 0; i < 4; i++) {
                float4 wv = w4[lid + i * 32];
                s = fmaf(hreg[i].x, wv.x, s);
                s = fmaf(hreg[i].y, wv.y, s);
                s = fmaf(hreg[i].z, wv.z, s);
                s = fmaf(hreg[i].w, wv.w, s);
            }
#pragma unroll
            for (int off = 16; off > 0; off >>= 1)
                s += __shfl_xor_sync(0xffffffffu, s, off);
            s += b[j];
            if (s > best || (s == best && j < bidx)) { best = s; bidx = j; }
        }
        bidx = __shfl_sync(0xffffffffu, bidx, 0);
    }

    const float4* src4 = (const float4*)(g_table + (size_t)bidx * O_DIM);
    float4* dst = (float4*)(out + (size_t)row * O_DIM);
#pragma unroll
    for (int i = 0; i < 4; i++)
        dst[lid + i * 32] = src4[lid + i * 32];
}

extern "C" void kernel_launch(void* const* d_in, const int* in_sizes, int n_in,
                              void* d_out, int out_size)
{
    const float* x     = (const float*)d_in[0];
    const float* i2m_w = (const float*)d_in[2];
    const float* i2m_b = (const float*)d_in[3];
    const float* m2h_w = (const float*)d_in[4];
    const float* m2h_b = (const float*)d_in[5];
    const float* h2o_w = (const float*)d_in[6];
    const float* h2o_b = (const float*)d_in[7];
    float* out = (float*)d_out;

    cudaFuncSetAttribute(gemm_fused, cudaFuncAttributeMaxDynamicSharedMemorySize, SMEM_DYN);

    // merged prep (also zeros rendezvous counters each launch/replay)
    prep<<<NB_PREP, 512>>>(x, i2m_w, m2h_w, h2o_w, h2o_b);

    // fused gemm1 + gemm2 with device-side acquire/release rendezvous
    gemm_fused<<<G1_BLOCKS + G2_BLOCKS, 128, SMEM_DYN>>>(i2m_b, m2h_b);

    // winner per row (fp32-verified when ambiguous) + output write
    scan_out<<<ROWS/8, 256>>>(m2h_w, m2h_b, out);
}